// round 11
// baseline (speedup 1.0000x reference)
#include <cuda_runtime.h>
#include <cuda_bf16.h>
#include <cstdint>

// Segment max-pool, double-buffered + channel-slab parallel:
//   point_features: (B, C, N) float32   [d_in[0]]
//   box_ids_of_pts: (B, N)    int32/int64 (auto-detected)  [d_in[2]]
//   out:            (B*S, C)  float32   S = 100
//
// Grid = (chunks, B, slabs). Per block: counting-sort its 2048-pt chunk's
// labels once; per 2-channel group: cp.async-prefetch group g+1 while
// reducing group g. Reduce task = (seg, quarter) covering BOTH channels:
// idx read once, fmaxf into both rows. Encoded-int atomicMax to output.

#define S_SEG    100
#define CHUNK    2048
#define NTHREADS 256
#define CG       2
#define SLABS    4
#define TILE_PAD 8

__device__ int g_lab_is_64;

__device__ __forceinline__ int enc_f32(float f) {
    int i = __float_as_int(f);
    return (i >= 0) ? i : (i ^ 0x7FFFFFFF);
}

__device__ __forceinline__ void cp_async16(void* smem_dst, const void* gmem_src) {
    unsigned sa = (unsigned)__cvta_generic_to_shared(smem_dst);
    asm volatile("cp.async.cg.shared.global [%0], [%1], 16;\n"
                 :: "r"(sa), "l"(gmem_src) : "memory");
}

// init output to enc(-inf); block0/thread0 also detects label dtype:
// int64 labels in [0,100) look like [lab,0,lab,0,...] as int32 words.
__global__ void init_out_kernel(int* __restrict__ outI, int n,
                                const int* __restrict__ lab32) {
    int i = blockIdx.x * blockDim.x + threadIdx.x;
    if (i < n) outI[i] = 0x807FFFFF;
    if (blockIdx.x == 0 && threadIdx.x == 0) {
        int is64 = 1;
        #pragma unroll 1
        for (int k = 0; k < 128; k++) {
            int lo = lab32[2 * k], hi = lab32[2 * k + 1];
            if (hi != 0 || lo < 0 || lo >= S_SEG) { is64 = 0; break; }
        }
        g_lab_is_64 = is64;
    }
}

__global__ void decode_out_kernel(float* __restrict__ outF, int n) {
    int i = blockIdx.x * blockDim.x + threadIdx.x;
    if (i < n) {
        int v = __float_as_int(outF[i]);
        outF[i] = __int_as_float((v >= 0) ? v : (v ^ 0x7FFFFFFF));
    }
}

__global__ __launch_bounds__(NTHREADS)
void seg_max_kernel(const float* __restrict__ pf,
                    const int* __restrict__ lab32,
                    int* __restrict__ outI,
                    int C, int N) {
    __shared__ __align__(16) float s_tile[2][CG][CHUNK + TILE_PAD];
    __shared__ __align__(16) unsigned short s_lab[CHUNK];
    __shared__ __align__(16) unsigned short s_idx[CHUNK];
    __shared__ int s_cnt[S_SEG];
    __shared__ int s_off[S_SEG + 1];
    __shared__ int s_cur[S_SEG];

    const int tid = threadIdx.x;
    const int b = blockIdx.y;
    const int chPerSlab = C / SLABS;           // 32
    const int chBase = blockIdx.z * chPerSlab;
    const int n0 = blockIdx.x * CHUNK;
    const int len = min(CHUNK, N - n0);
    const int is64 = g_lab_is_64;

    for (int s = tid; s < S_SEG; s += NTHREADS) s_cnt[s] = 0;
    __syncthreads();

    // ---- labels + histogram (dtype-agnostic) ----
    {
        const size_t base = (size_t)b * N + n0;
        for (int i = tid; i < len; i += NTHREADS) {
            long long l;
            if (is64) {
                int2 w = ((const int2*)lab32)[base + i];
                l = ((long long)w.y << 32) | (unsigned int)w.x;
            } else {
                l = lab32[base + i];
            }
            if (l >= 0 && l < S_SEG) {
                s_lab[i] = (unsigned short)l;
                atomicAdd(&s_cnt[(int)l], 1);
            } else {
                s_lab[i] = 0xFFFF;
            }
        }
    }
    __syncthreads();

    if (tid == 0) {
        int run = 0;
        #pragma unroll 4
        for (int s = 0; s < S_SEG; s++) { s_off[s] = run; run += s_cnt[s]; }
        s_off[S_SEG] = run;
    }
    __syncthreads();
    for (int s = tid; s < S_SEG; s += NTHREADS) s_cur[s] = s_off[s];
    __syncthreads();

    for (int i = tid; i < len; i += NTHREADS) {
        unsigned short l = s_lab[i];
        if (l != 0xFFFF) {
            int pos = atomicAdd(&s_cur[l], 1);
            s_idx[pos] = (unsigned short)i;
        }
    }
    __syncthreads();

    // ---- double-buffered channel groups within this slab ----
    const int nGroups = chPerSlab / CG;        // 16
    const int lenAligned = len & ~3;
    const int nVec = (CHUNK / 4) * CG;

    auto stage = [&](int g, int buf) {
        const int ch0 = chBase + g * CG;
        #pragma unroll 2
        for (int k = tid; k < nVec; k += NTHREADS) {
            const int e = k * 4;
            const int cl = e / CHUNK;
            const int i = e & (CHUNK - 1);
            if (i < lenAligned) {
                const float* src = pf + (((size_t)b * C + ch0 + cl) * N + n0 + i);
                cp_async16(&s_tile[buf][cl][i], src);
            }
        }
        asm volatile("cp.async.commit_group;\n" ::: "memory");
    };

    stage(0, 0);

    for (int g = 0; g < nGroups; g++) {
        const int buf = g & 1;
        if (g + 1 < nGroups) {
            stage(g + 1, buf ^ 1);
            asm volatile("cp.async.wait_group 1;\n" ::: "memory");
        } else {
            asm volatile("cp.async.wait_group 0;\n" ::: "memory");
        }
        __syncthreads();

        // scalar tail (len % 4 != 0) — never taken for N = 65536
        if (lenAligned < len) {
            const int ch0 = chBase + g * CG;
            #pragma unroll
            for (int cl = 0; cl < CG; cl++) {
                const float* src = pf + (((size_t)b * C + ch0 + cl) * N + n0);
                for (int i = lenAligned + tid; i < len; i += NTHREADS)
                    s_tile[buf][cl][i] = src[i];
            }
            __syncthreads();
        }

        // reduce: task = (seg, quarter); each task covers BOTH channels so
        // the idx load is amortized (3 LDS/point instead of 4). 400 tasks.
        const int ch0 = chBase + g * CG;
        for (int task = tid; task < S_SEG * 4; task += NTHREADS) {
            const int seg = task >> 2;
            const int q = task & 3;
            const int q0 = s_off[seg];
            const int cnt = s_off[seg + 1] - q0;
            const int p0 = q0 + ((cnt * q) >> 2);
            const int p1 = q0 + ((cnt * (q + 1)) >> 2);
            if (p0 < p1) {
                float m0 = -__int_as_float(0x7F800000);
                float m1 = m0;
                const float* row0 = &s_tile[buf][0][0];
                const float* row1 = &s_tile[buf][1][0];
                #pragma unroll 4
                for (int p = p0; p < p1; p++) {
                    const int idx = s_idx[p];
                    m0 = fmaxf(m0, row0[idx]);
                    m1 = fmaxf(m1, row1[idx]);
                }
                int* cell = &outI[((size_t)(b * S_SEG + seg)) * C + ch0];
                atomicMax(cell, enc_f32(m0));
                atomicMax(cell + 1, enc_f32(m1));
            }
        }
        __syncthreads();   // buffer reused two iterations later
    }
}

extern "C" void kernel_launch(void* const* d_in, const int* in_sizes, int n_in,
                              void* d_out, int out_size) {
    const float* pf = (const float*)d_in[0];
    const int* lab32 = (const int*)d_in[2];

    const int pf_elems = in_sizes[0];      // B*C*N
    const int lab_elems = in_sizes[2];     // B*N
    const int C = pf_elems / lab_elems;    // 128
    const int B = out_size / (S_SEG * C);  // 8
    const int N = lab_elems / B;           // 65536

    int* outI = (int*)d_out;
    float* outF = (float*)d_out;

    const int initBlocks = (out_size + 255) / 256;
    init_out_kernel<<<initBlocks, 256>>>(outI, out_size, lab32);

    const int numChunks = (N + CHUNK - 1) / CHUNK;
    dim3 grid(numChunks, B, SLABS);
    seg_max_kernel<<<grid, NTHREADS>>>(pf, lab32, outI, C, N);

    decode_out_kernel<<<initBlocks, 256>>>(outF, out_size);
}

// round 12
// speedup vs baseline: 1.9520x; 1.9520x over previous
#include <cuda_runtime.h>
#include <cuda_bf16.h>
#include <cstdint>

// Segment max-pool, double-buffered + channel-slab parallel (R6 baseline):
//   point_features: (B, C, N) float32   [d_in[0]]
//   box_ids_of_pts: (B, N)    int32/int64 (auto-detected)  [d_in[2]]
//   out:            (B*S, C)  float32   S = 100
//
// Grid = (chunks, B, slabs). Each block: counting-sort its 2048-pt chunk's
// labels once, then for its 32-channel slab, cp.async-prefetch group g+1
// while reducing group g (fmaxf over LDS gathers), one encoded-int atomicMax
// per (seg, half, ch, block). Float max via monotone-int encoding.

#define S_SEG    100
#define CHUNK    2048
#define NTHREADS 256
#define CG       2
#define SLABS    4
#define TILE_PAD 8

__device__ int g_lab_is_64;

__device__ __forceinline__ int enc_f32(float f) {
    int i = __float_as_int(f);
    return (i >= 0) ? i : (i ^ 0x7FFFFFFF);
}

__device__ __forceinline__ void cp_async16(void* smem_dst, const void* gmem_src) {
    unsigned sa = (unsigned)__cvta_generic_to_shared(smem_dst);
    asm volatile("cp.async.cg.shared.global [%0], [%1], 16;\n"
                 :: "r"(sa), "l"(gmem_src) : "memory");
}

// init output to enc(-inf); block0/thread0 also detects label dtype:
// int64 labels in [0,100) look like [lab,0,lab,0,...] as int32 words.
__global__ void init_out_kernel(int* __restrict__ outI, int n,
                                const int* __restrict__ lab32) {
    int i = blockIdx.x * blockDim.x + threadIdx.x;
    if (i < n) outI[i] = 0x807FFFFF;
    if (blockIdx.x == 0 && threadIdx.x == 0) {
        int is64 = 1;
        #pragma unroll 1
        for (int k = 0; k < 128; k++) {
            int lo = lab32[2 * k], hi = lab32[2 * k + 1];
            if (hi != 0 || lo < 0 || lo >= S_SEG) { is64 = 0; break; }
        }
        g_lab_is_64 = is64;
    }
}

__global__ void decode_out_kernel(float* __restrict__ outF, int n) {
    int i = blockIdx.x * blockDim.x + threadIdx.x;
    if (i < n) {
        int v = __float_as_int(outF[i]);
        outF[i] = __int_as_float((v >= 0) ? v : (v ^ 0x7FFFFFFF));
    }
}

__global__ __launch_bounds__(NTHREADS)
void seg_max_kernel(const float* __restrict__ pf,
                    const int* __restrict__ lab32,
                    int* __restrict__ outI,
                    int C, int N) {
    __shared__ __align__(16) float s_tile[2][CG][CHUNK + TILE_PAD];
    __shared__ __align__(16) unsigned short s_lab[CHUNK];
    __shared__ __align__(16) unsigned short s_idx[CHUNK];
    __shared__ int s_cnt[S_SEG];
    __shared__ int s_off[S_SEG + 1];
    __shared__ int s_cur[S_SEG];

    const int tid = threadIdx.x;
    const int b = blockIdx.y;
    const int chPerSlab = C / SLABS;           // 32
    const int chBase = blockIdx.z * chPerSlab;
    const int n0 = blockIdx.x * CHUNK;
    const int len = min(CHUNK, N - n0);
    const int is64 = g_lab_is_64;

    for (int s = tid; s < S_SEG; s += NTHREADS) s_cnt[s] = 0;
    __syncthreads();

    // ---- labels + histogram (dtype-agnostic) ----
    {
        const size_t base = (size_t)b * N + n0;
        for (int i = tid; i < len; i += NTHREADS) {
            long long l;
            if (is64) {
                int2 w = ((const int2*)lab32)[base + i];
                l = ((long long)w.y << 32) | (unsigned int)w.x;
            } else {
                l = lab32[base + i];
            }
            if (l >= 0 && l < S_SEG) {
                s_lab[i] = (unsigned short)l;
                atomicAdd(&s_cnt[(int)l], 1);
            } else {
                s_lab[i] = 0xFFFF;
            }
        }
    }
    __syncthreads();

    if (tid == 0) {
        int run = 0;
        #pragma unroll 4
        for (int s = 0; s < S_SEG; s++) { s_off[s] = run; run += s_cnt[s]; }
        s_off[S_SEG] = run;
    }
    __syncthreads();
    for (int s = tid; s < S_SEG; s += NTHREADS) s_cur[s] = s_off[s];
    __syncthreads();

    for (int i = tid; i < len; i += NTHREADS) {
        unsigned short l = s_lab[i];
        if (l != 0xFFFF) {
            int pos = atomicAdd(&s_cur[l], 1);
            s_idx[pos] = (unsigned short)i;
        }
    }
    __syncthreads();

    // ---- double-buffered channel groups within this slab ----
    const int nGroups = chPerSlab / CG;        // 16
    const int lenAligned = len & ~3;
    const int nVec = (CHUNK / 4) * CG;

    auto stage = [&](int g, int buf) {
        const int ch0 = chBase + g * CG;
        #pragma unroll 2
        for (int k = tid; k < nVec; k += NTHREADS) {
            const int e = k * 4;
            const int cl = e / CHUNK;
            const int i = e & (CHUNK - 1);
            if (i < lenAligned) {
                const float* src = pf + (((size_t)b * C + ch0 + cl) * N + n0 + i);
                cp_async16(&s_tile[buf][cl][i], src);
            }
        }
        asm volatile("cp.async.commit_group;\n" ::: "memory");
    };

    stage(0, 0);

    for (int g = 0; g < nGroups; g++) {
        const int buf = g & 1;
        if (g + 1 < nGroups) {
            stage(g + 1, buf ^ 1);
            asm volatile("cp.async.wait_group 1;\n" ::: "memory");
        } else {
            asm volatile("cp.async.wait_group 0;\n" ::: "memory");
        }
        __syncthreads();

        // scalar tail (len % 4 != 0) — never taken for N = 65536
        if (lenAligned < len) {
            const int ch0 = chBase + g * CG;
            #pragma unroll
            for (int cl = 0; cl < CG; cl++) {
                const float* src = pf + (((size_t)b * C + ch0 + cl) * N + n0);
                for (int i = lenAligned + tid; i < len; i += NTHREADS)
                    s_tile[buf][cl][i] = src[i];
            }
            __syncthreads();
        }

        // reduce: task = (seg, half, channel-in-group); 400 tasks
        const int ch0 = chBase + g * CG;
        for (int task = tid; task < S_SEG * 2 * CG; task += NTHREADS) {
            const int seg = task >> 2;         // 2*CG == 4 subtasks per seg
            const int sub = task & 3;
            const int cl = sub & 1;
            const int half = sub >> 1;
            const int q0 = s_off[seg];
            const int q1 = s_off[seg + 1];
            const int mid = (q0 + q1 + 1) >> 1;
            const int p0 = half ? mid : q0;
            const int p1 = half ? q1 : mid;
            if (p0 < p1) {
                float m = -__int_as_float(0x7F800000);
                const float* row = &s_tile[buf][cl][0];
                #pragma unroll 4
                for (int p = p0; p < p1; p++)
                    m = fmaxf(m, row[s_idx[p]]);
                atomicMax(&outI[((size_t)(b * S_SEG + seg)) * C + ch0 + cl],
                          enc_f32(m));
            }
        }
        __syncthreads();   // buffer reused two iterations later
    }
}

extern "C" void kernel_launch(void* const* d_in, const int* in_sizes, int n_in,
                              void* d_out, int out_size) {
    const float* pf = (const float*)d_in[0];
    const int* lab32 = (const int*)d_in[2];

    const int pf_elems = in_sizes[0];      // B*C*N
    const int lab_elems = in_sizes[2];     // B*N
    const int C = pf_elems / lab_elems;    // 128
    const int B = out_size / (S_SEG * C);  // 8
    const int N = lab_elems / B;           // 65536

    int* outI = (int*)d_out;
    float* outF = (float*)d_out;

    const int initBlocks = (out_size + 255) / 256;
    init_out_kernel<<<initBlocks, 256>>>(outI, out_size, lab32);

    const int numChunks = (N + CHUNK - 1) / CHUNK;
    dim3 grid(numChunks, B, SLABS);
    seg_max_kernel<<<grid, NTHREADS>>>(pf, lab32, outI, C, N);

    decode_out_kernel<<<initBlocks, 256>>>(outF, out_size);
}

// round 13
// speedup vs baseline: 2.0395x; 1.0448x over previous
#include <cuda_runtime.h>
#include <cuda_bf16.h>
#include <cstdint>

// Segment max-pool, double-buffered + channel-slab parallel (SLABS=8):
//   point_features: (B, C, N) float32   [d_in[0]]
//   box_ids_of_pts: (B, N)    int32/int64 (auto-detected)  [d_in[2]]
//   out:            (B*S, C)  float32   S = 100
//
// Grid = (chunks, B, slabs). Each block: counting-sort its 2048-pt chunk's
// labels once, then for its 16-channel slab, cp.async-prefetch group g+1
// while reducing group g (fmaxf over LDS gathers), one encoded-int atomicMax
// per (seg, half, ch, block). Float max via monotone-int encoding.

#define S_SEG    100
#define CHUNK    2048
#define NTHREADS 256
#define CG       2
#define SLABS    8
#define TILE_PAD 8

__device__ int g_lab_is_64;

__device__ __forceinline__ int enc_f32(float f) {
    int i = __float_as_int(f);
    return (i >= 0) ? i : (i ^ 0x7FFFFFFF);
}

__device__ __forceinline__ void cp_async16(void* smem_dst, const void* gmem_src) {
    unsigned sa = (unsigned)__cvta_generic_to_shared(smem_dst);
    asm volatile("cp.async.cg.shared.global [%0], [%1], 16;\n"
                 :: "r"(sa), "l"(gmem_src) : "memory");
}

// init output to enc(-inf); block0/thread0 also detects label dtype:
// int64 labels in [0,100) look like [lab,0,lab,0,...] as int32 words.
__global__ void init_out_kernel(int* __restrict__ outI, int n,
                                const int* __restrict__ lab32) {
    int i = blockIdx.x * blockDim.x + threadIdx.x;
    if (i < n) outI[i] = 0x807FFFFF;
    if (blockIdx.x == 0 && threadIdx.x == 0) {
        int is64 = 1;
        #pragma unroll 1
        for (int k = 0; k < 128; k++) {
            int lo = lab32[2 * k], hi = lab32[2 * k + 1];
            if (hi != 0 || lo < 0 || lo >= S_SEG) { is64 = 0; break; }
        }
        g_lab_is_64 = is64;
    }
}

__global__ void decode_out_kernel(float* __restrict__ outF, int n) {
    int i = blockIdx.x * blockDim.x + threadIdx.x;
    if (i < n) {
        int v = __float_as_int(outF[i]);
        outF[i] = __int_as_float((v >= 0) ? v : (v ^ 0x7FFFFFFF));
    }
}

__global__ __launch_bounds__(NTHREADS)
void seg_max_kernel(const float* __restrict__ pf,
                    const int* __restrict__ lab32,
                    int* __restrict__ outI,
                    int C, int N) {
    __shared__ __align__(16) float s_tile[2][CG][CHUNK + TILE_PAD];
    __shared__ __align__(16) unsigned short s_lab[CHUNK];
    __shared__ __align__(16) unsigned short s_idx[CHUNK];
    __shared__ int s_cnt[S_SEG];
    __shared__ int s_off[S_SEG + 1];
    __shared__ int s_cur[S_SEG];

    const int tid = threadIdx.x;
    const int b = blockIdx.y;
    const int chPerSlab = C / SLABS;           // 16
    const int chBase = blockIdx.z * chPerSlab;
    const int n0 = blockIdx.x * CHUNK;
    const int len = min(CHUNK, N - n0);
    const int is64 = g_lab_is_64;

    for (int s = tid; s < S_SEG; s += NTHREADS) s_cnt[s] = 0;
    __syncthreads();

    // ---- labels + histogram (dtype-agnostic) ----
    {
        const size_t base = (size_t)b * N + n0;
        for (int i = tid; i < len; i += NTHREADS) {
            long long l;
            if (is64) {
                int2 w = ((const int2*)lab32)[base + i];
                l = ((long long)w.y << 32) | (unsigned int)w.x;
            } else {
                l = lab32[base + i];
            }
            if (l >= 0 && l < S_SEG) {
                s_lab[i] = (unsigned short)l;
                atomicAdd(&s_cnt[(int)l], 1);
            } else {
                s_lab[i] = 0xFFFF;
            }
        }
    }
    __syncthreads();

    if (tid == 0) {
        int run = 0;
        #pragma unroll 4
        for (int s = 0; s < S_SEG; s++) { s_off[s] = run; run += s_cnt[s]; }
        s_off[S_SEG] = run;
    }
    __syncthreads();
    for (int s = tid; s < S_SEG; s += NTHREADS) s_cur[s] = s_off[s];
    __syncthreads();

    for (int i = tid; i < len; i += NTHREADS) {
        unsigned short l = s_lab[i];
        if (l != 0xFFFF) {
            int pos = atomicAdd(&s_cur[l], 1);
            s_idx[pos] = (unsigned short)i;
        }
    }
    __syncthreads();

    // ---- double-buffered channel groups within this slab ----
    const int nGroups = chPerSlab / CG;        // 8
    const int lenAligned = len & ~3;
    const int nVec = (CHUNK / 4) * CG;

    auto stage = [&](int g, int buf) {
        const int ch0 = chBase + g * CG;
        #pragma unroll 2
        for (int k = tid; k < nVec; k += NTHREADS) {
            const int e = k * 4;
            const int cl = e / CHUNK;
            const int i = e & (CHUNK - 1);
            if (i < lenAligned) {
                const float* src = pf + (((size_t)b * C + ch0 + cl) * N + n0 + i);
                cp_async16(&s_tile[buf][cl][i], src);
            }
        }
        asm volatile("cp.async.commit_group;\n" ::: "memory");
    };

    stage(0, 0);

    for (int g = 0; g < nGroups; g++) {
        const int buf = g & 1;
        if (g + 1 < nGroups) {
            stage(g + 1, buf ^ 1);
            asm volatile("cp.async.wait_group 1;\n" ::: "memory");
        } else {
            asm volatile("cp.async.wait_group 0;\n" ::: "memory");
        }
        __syncthreads();

        // scalar tail (len % 4 != 0) — never taken for N = 65536
        if (lenAligned < len) {
            const int ch0 = chBase + g * CG;
            #pragma unroll
            for (int cl = 0; cl < CG; cl++) {
                const float* src = pf + (((size_t)b * C + ch0 + cl) * N + n0);
                for (int i = lenAligned + tid; i < len; i += NTHREADS)
                    s_tile[buf][cl][i] = src[i];
            }
            __syncthreads();
        }

        // reduce: task = (seg, half, channel-in-group); 400 tasks
        const int ch0 = chBase + g * CG;
        for (int task = tid; task < S_SEG * 2 * CG; task += NTHREADS) {
            const int seg = task >> 2;         // 2*CG == 4 subtasks per seg
            const int sub = task & 3;
            const int cl = sub & 1;
            const int half = sub >> 1;
            const int q0 = s_off[seg];
            const int q1 = s_off[seg + 1];
            const int mid = (q0 + q1 + 1) >> 1;
            const int p0 = half ? mid : q0;
            const int p1 = half ? q1 : mid;
            if (p0 < p1) {
                float m = -__int_as_float(0x7F800000);
                const float* row = &s_tile[buf][cl][0];
                #pragma unroll 4
                for (int p = p0; p < p1; p++)
                    m = fmaxf(m, row[s_idx[p]]);
                atomicMax(&outI[((size_t)(b * S_SEG + seg)) * C + ch0 + cl],
                          enc_f32(m));
            }
        }
        __syncthreads();   // buffer reused two iterations later
    }
}

extern "C" void kernel_launch(void* const* d_in, const int* in_sizes, int n_in,
                              void* d_out, int out_size) {
    const float* pf = (const float*)d_in[0];
    const int* lab32 = (const int*)d_in[2];

    const int pf_elems = in_sizes[0];      // B*C*N
    const int lab_elems = in_sizes[2];     // B*N
    const int C = pf_elems / lab_elems;    // 128
    const int B = out_size / (S_SEG * C);  // 8
    const int N = lab_elems / B;           // 65536

    int* outI = (int*)d_out;
    float* outF = (float*)d_out;

    const int initBlocks = (out_size + 255) / 256;
    init_out_kernel<<<initBlocks, 256>>>(outI, out_size, lab32);

    const int numChunks = (N + CHUNK - 1) / CHUNK;
    dim3 grid(numChunks, B, SLABS);
    seg_max_kernel<<<grid, NTHREADS>>>(pf, lab32, outI, C, N);

    decode_out_kernel<<<initBlocks, 256>>>(outF, out_size);
}